// round 11
// baseline (speedup 1.0000x reference)
#include <cuda_runtime.h>

// Problem constants (fixed by the dataset): N=50000, NIN=128, NOUT=64, H=4, C=16, E=800000
#define MAXN 50000
#define MAXE 800000
#define MAXET (MAXE + MAXN)   // edges + self-loops
#define NH   4      // heads
#define NC   16     // channels per head
#define NOUT 64     // NH*NC

// Scratch (allocation-free rule: __device__ globals)
__device__ __align__(16) float g_xw[MAXN * NOUT];      // 12.8 MB
__device__ __align__(16) float g_as[MAXN * NH];
__device__ __align__(16) float g_ad[MAXN * NH];
__device__ __align__(16) float g_den[MAXN * NH];
__device__ __align__(16) float g_alp[MAXET * NH];      // unnormalized e per edge, 13.6 MB
__device__ __align__(16) int2  g_sd[MAXET];            // packed (src,dst), 6.8 MB
__device__ __align__(16) int   g_cnt[MAXN];            // in-degree / cursor
__device__ __align__(16) int   g_start[MAXN + 1];      // CSR offsets
__device__ __align__(16) int   g_csr_src[MAXET];       // CSR payload: src
__device__ __align__(16) float g_csr_e[MAXET * NH];    // CSR payload: e[4]
__device__ int g_is64;                                 // edge_index dtype flag

__device__ __forceinline__ float lrelu(float v) {
    return v > 0.f ? v : 0.2f * v;
}

// Vectorized global reduction: one instruction, 16 bytes (sm_90+).
__device__ __forceinline__ void red_add_v4(float* p, float4 m) {
    asm volatile("red.global.add.v4.f32 [%0], {%1, %2, %3, %4};"
                 :: "l"(p), "f"(m.x), "f"(m.y), "f"(m.z), "f"(m.w)
                 : "memory");
}

// ---------------------------------------------------------------------------
// K0: detect edge_index element width. For little-endian int64 indices in
// [0, 2^31), every odd 32-bit word is 0. For int32 edge data, odd words are
// uniform node ids in [0, 50000) — 4096 consecutive zeros is impossible.
// ---------------------------------------------------------------------------
__global__ void detect_kernel(const int* __restrict__ ei32)
{
    __shared__ int any_nonzero;
    if (threadIdx.x == 0) any_nonzero = 0;
    __syncthreads();
    for (int i = threadIdx.x; i < 4096; i += blockDim.x)
        if (ei32[2 * i + 1] != 0) any_nonzero = 1;
    __syncthreads();
    if (threadIdx.x == 0) g_is64 = (any_nonzero == 0) ? 1 : 0;
}

// ---------------------------------------------------------------------------
// K1: xw = x @ W ([n,128]@[128,64]) with fused attention-logit epilogue.
// 32 rows/block, 256 threads. Epilogue also zeroes g_den and g_cnt.
// ---------------------------------------------------------------------------
__global__ void gemm_kernel(const float* __restrict__ x,
                            const float* __restrict__ W,
                            const float* __restrict__ att_src,
                            const float* __restrict__ att_dst, int n)
{
    __shared__ float Xs[32][68];   // pad 68: no bank conflicts
    __shared__ float Ws[64][64];

    const int t  = threadIdx.x;
    const int tx = t & 15;         // col group (cols tx*4 .. tx*4+3)
    const int ty = t >> 4;         // row group (rows ty*2, ty*2+1)
    const int row0 = blockIdx.x * 32;

    float acc[2][4] = {{0.f,0.f,0.f,0.f},{0.f,0.f,0.f,0.f}};

    for (int kc = 0; kc < 128; kc += 64) {
        #pragma unroll
        for (int i = 0; i < 4; i++) {
            int idx4 = t + i * 256;
            int kr = idx4 >> 4;
            int c4 = (idx4 & 15) << 2;
            *(float4*)&Ws[kr][c4] = *(const float4*)&W[(kc + kr) * NOUT + c4];
        }
        #pragma unroll
        for (int i = 0; i < 2; i++) {
            int idx4 = t + i * 256;
            int r  = idx4 >> 4;
            int c4 = (idx4 & 15) << 2;
            float4 v = make_float4(0.f, 0.f, 0.f, 0.f);
            if (row0 + r < n)
                v = *(const float4*)&x[(size_t)(row0 + r) * 128 + kc + c4];
            *(float4*)&Xs[r][c4] = v;
        }
        __syncthreads();

        #pragma unroll 16
        for (int k = 0; k < 64; k++) {
            float4 b = *(float4*)&Ws[k][tx << 2];
            float a0 = Xs[ty * 2 + 0][k];
            float a1 = Xs[ty * 2 + 1][k];
            acc[0][0] = fmaf(a0, b.x, acc[0][0]);
            acc[0][1] = fmaf(a0, b.y, acc[0][1]);
            acc[0][2] = fmaf(a0, b.z, acc[0][2]);
            acc[0][3] = fmaf(a0, b.w, acc[0][3]);
            acc[1][0] = fmaf(a1, b.x, acc[1][0]);
            acc[1][1] = fmaf(a1, b.y, acc[1][1]);
            acc[1][2] = fmaf(a1, b.z, acc[1][2]);
            acc[1][3] = fmaf(a1, b.w, acc[1][3]);
        }
        __syncthreads();
    }

    #pragma unroll
    for (int i = 0; i < 2; i++) {
        int r = row0 + ty * 2 + i;
        if (r < n) {
            float4 v = make_float4(acc[i][0], acc[i][1], acc[i][2], acc[i][3]);
            *(float4*)&g_xw[(size_t)r * NOUT + (tx << 2)] = v;
        }
    }

    // Fused attention-logit epilogue; lanes of a (row,head) group differ
    // in lane-id bits 0,1 (same warp), reduce with shfl_xor 1,2.
    const int h  = tx >> 2;
    const int co = (tx & 3) << 2;
    float4 sa = __ldg((const float4*)&att_src[h * NC + co]);
    float4 da = __ldg((const float4*)&att_dst[h * NC + co]);

    #pragma unroll
    for (int i = 0; i < 2; i++) {
        float ps = acc[i][0]*sa.x + acc[i][1]*sa.y + acc[i][2]*sa.z + acc[i][3]*sa.w;
        float pd = acc[i][0]*da.x + acc[i][1]*da.y + acc[i][2]*da.z + acc[i][3]*da.w;
        ps += __shfl_xor_sync(0xffffffffu, ps, 1);
        pd += __shfl_xor_sync(0xffffffffu, pd, 1);
        ps += __shfl_xor_sync(0xffffffffu, ps, 2);
        pd += __shfl_xor_sync(0xffffffffu, pd, 2);
        int r = row0 + ty * 2 + i;
        if ((tx & 3) == 0 && r < n) {
            g_as[r * NH + h]  = ps;
            g_ad[r * NH + h]  = pd;
            g_den[r * NH + h] = 0.f;
            if (h == 0) g_cnt[r] = 0;
        }
    }
}

// ---------------------------------------------------------------------------
// K2: per-edge e = exp(lrelu(a_src[s]+a_dst[d])); store e + (src,dst);
// accumulate denominator; histogram in-degree. Handles int64/int32 edge
// layouts via g_is64. Indices clamped (no-op for valid graphs).
// No max-shift needed: logits ~N(0,2), fp32-safe; alpha shift-invariant.
// ---------------------------------------------------------------------------
__global__ void denom_kernel(const void* __restrict__ eiv, int n, int e)
{
    int i = blockIdx.x * blockDim.x + threadIdx.x;
    int etot = e + n;
    if (i >= etot) return;
    int s, d;
    if (i < e) {
        if (g_is64) {
            const long long* ei = (const long long*)eiv;
            s = (int)__ldg(&ei[i]); d = (int)__ldg(&ei[e + i]);
        } else {
            const int* ei = (const int*)eiv;
            s = __ldg(&ei[i]); d = __ldg(&ei[e + i]);
        }
        s = min(max(s, 0), n - 1);
        d = min(max(d, 0), n - 1);
    } else {
        s = i - e; d = s;
    }
    g_sd[i] = make_int2(s, d);

    float4 as = __ldg(&((const float4*)g_as)[s]);
    float4 ad = __ldg(&((const float4*)g_ad)[d]);
    float4 ev;
    ev.x = __expf(lrelu(as.x + ad.x));
    ev.y = __expf(lrelu(as.y + ad.y));
    ev.z = __expf(lrelu(as.z + ad.z));
    ev.w = __expf(lrelu(as.w + ad.w));
    ((float4*)g_alp)[i] = ev;
    red_add_v4(&g_den[d * NH], ev);
    atomicAdd(&g_cnt[d], 1);
}

// ---------------------------------------------------------------------------
// K3: exclusive scan of g_cnt -> g_start (single block, 1024 threads),
// and re-zero g_cnt for use as the permute cursor.
// ---------------------------------------------------------------------------
__global__ void scan_kernel(int n)
{
    __shared__ int part[1024];
    const int t  = threadIdx.x;
    const int CH = (n + 1023) / 1024;          // 49 for n=50000
    const int base = t * CH;

    int s = 0;
    for (int j = 0; j < CH; j++) {
        int idx = base + j;
        if (idx < n) s += g_cnt[idx];
    }
    part[t] = s;
    __syncthreads();
    // Hillis-Steele inclusive scan over 1024 partials
    for (int off = 1; off < 1024; off <<= 1) {
        int v = (t >= off) ? part[t - off] : 0;
        __syncthreads();
        part[t] += v;
        __syncthreads();
    }
    int run = (t == 0) ? 0 : part[t - 1];
    for (int j = 0; j < CH; j++) {
        int idx = base + j;
        if (idx < n) {
            g_start[idx] = run;
            run += g_cnt[idx];
            g_cnt[idx] = 0;                    // reset as cursor
        }
    }
    if (t == 1023) g_start[n] = part[1023];
}

// ---------------------------------------------------------------------------
// K4: permute edges into dst-CSR order: payload (src, e[4]) per slot.
// Intra-segment order is scheduling-dependent; downstream sums differ only
// in association order (~1e-7), far inside the 1e-3 tolerance.
// ---------------------------------------------------------------------------
__global__ void permute_kernel(int etot)
{
    int i = blockIdx.x * blockDim.x + threadIdx.x;
    if (i >= etot) return;
    int2 sd = __ldg(&g_sd[i]);
    int slot = __ldg(&g_start[sd.y]) + atomicAdd(&g_cnt[sd.y], 1);
    g_csr_src[slot] = sd.x;
    ((float4*)g_csr_e)[slot] = __ldg(&((const float4*)g_alp)[i]);
}

// ---------------------------------------------------------------------------
// K5: aggregate — one warp per destination node. Lane = (edge-group, quad):
// groups 0/1 process alternating edges; lane q owns channels q*4..q*4+3.
// Registers accumulate sum(e * xw[src]); divide by den once; add bias; one
// STG.128 per quad. Zero floating-point atomics. unroll 2 -> 2 outstanding
// xw gathers per lane (halves exposed L2 latency on the serial edge walk).
// ---------------------------------------------------------------------------
__global__ void aggregate_kernel(float* __restrict__ out,
                                 const float* __restrict__ bias, int n)
{
    int w = (blockIdx.x * blockDim.x + threadIdx.x) >> 5;   // dst node
    if (w >= n) return;
    const int lane = threadIdx.x & 31;
    const int grp  = lane >> 4;      // 0 or 1
    const int q    = lane & 15;      // quad
    const int h    = q >> 2;         // head

    const int beg = __ldg(&g_start[w]);
    const int end = __ldg(&g_start[w + 1]);

    float4 acc = make_float4(0.f, 0.f, 0.f, 0.f);
    #pragma unroll 2
    for (int j = beg + grp; j < end; j += 2) {
        int   src = __ldg(&g_csr_src[j]);
        float ev  = __ldg(&g_csr_e[4 * j + h]);
        float4 xw = __ldg((const float4*)&g_xw[(size_t)src * NOUT + (q << 2)]);
        acc.x = fmaf(ev, xw.x, acc.x);
        acc.y = fmaf(ev, xw.y, acc.y);
        acc.z = fmaf(ev, xw.z, acc.z);
        acc.w = fmaf(ev, xw.w, acc.w);
    }
    // combine the two edge-groups
    acc.x += __shfl_xor_sync(0xffffffffu, acc.x, 16);
    acc.y += __shfl_xor_sync(0xffffffffu, acc.y, 16);
    acc.z += __shfl_xor_sync(0xffffffffu, acc.z, 16);
    acc.w += __shfl_xor_sync(0xffffffffu, acc.w, 16);

    if (grp == 0) {
        float den = __ldg(&g_den[w * NH + h]);
        float r = 1.0f / (den + 1e-16f);
        float4 b = __ldg((const float4*)&bias[q << 2]);
        float4 o = make_float4(fmaf(acc.x, r, b.x), fmaf(acc.y, r, b.y),
                               fmaf(acc.z, r, b.z), fmaf(acc.w, r, b.w));
        *(float4*)&out[(size_t)w * NOUT + (q << 2)] = o;
    }
}

// ---------------------------------------------------------------------------
extern "C" void kernel_launch(void* const* d_in, const int* in_sizes, int n_in,
                              void* d_out, int out_size)
{
    const float* x       = (const float*)d_in[0];
    const void*  ei      = d_in[1];                 // [2, E], int64 OR int32 (detected)
    // d_in[2] = edge_attr (ignored by the layer)
    const float* W       = (const float*)d_in[3];
    const float* att_src = (const float*)d_in[4];
    const float* att_dst = (const float*)d_in[5];
    const float* bias    = (const float*)d_in[6];
    float*       out     = (float*)d_out;

    int n = in_sizes[0] / 128;   // 50000
    int e = in_sizes[1] / 2;     // 800000
    int etot = e + n;

    detect_kernel<<<1, 256>>>((const int*)ei);
    gemm_kernel<<<(n + 31) / 32, 256>>>(x, W, att_src, att_dst, n);
    denom_kernel<<<(etot + 255) / 256, 256>>>(ei, n, e);
    scan_kernel<<<1, 1024>>>(n);
    permute_kernel<<<(etot + 255) / 256, 256>>>(etot);
    aggregate_kernel<<<(n * 32 + 255) / 256, 256>>>(out, bias, n);
}

// round 13
// speedup vs baseline: 1.6067x; 1.6067x over previous
#include <cuda_runtime.h>

// Problem constants (fixed by the dataset): N=50000, NIN=128, NOUT=64, H=4, C=16, E=800000
#define MAXN 50000
#define MAXE 800000
#define MAXET (MAXE + MAXN)   // edges + self-loops
#define NH   4      // heads
#define NC   16     // channels per head
#define NOUT 64     // NH*NC
#define SCAN_B 1024
#define NBLK  ((MAXN + SCAN_B - 1) / SCAN_B)   // 49

// Scratch (allocation-free rule: __device__ globals)
__device__ __align__(16) float g_xw[MAXN * NOUT];      // 12.8 MB
__device__ __align__(16) float g_as[MAXN * NH];
__device__ __align__(16) float g_ad[MAXN * NH];
__device__ __align__(16) float g_den[MAXN * NH];
__device__ __align__(16) float g_alp[MAXET * NH];      // unnormalized e per edge, 13.6 MB
__device__ __align__(16) int2  g_sd[MAXET];            // packed (src,dst), 6.8 MB
__device__ __align__(16) int   g_cnt[MAXN];            // in-degree / cursor
__device__ __align__(16) int   g_start[MAXN + 1];      // CSR offsets
__device__ __align__(16) int   g_csr_src[MAXET];       // CSR payload: src
__device__ __align__(16) float g_csr_e[MAXET * NH];    // CSR payload: e[4]
__device__ __align__(16) int   g_bsum[64];             // per-block sums
__device__ __align__(16) int   g_boff[64];             // per-block offsets
__device__ int g_is64;                                 // edge_index dtype flag

__device__ __forceinline__ float lrelu(float v) {
    return v > 0.f ? v : 0.2f * v;
}

// Vectorized global reduction: one instruction, 16 bytes (sm_90+).
__device__ __forceinline__ void red_add_v4(float* p, float4 m) {
    asm volatile("red.global.add.v4.f32 [%0], {%1, %2, %3, %4};"
                 :: "l"(p), "f"(m.x), "f"(m.y), "f"(m.z), "f"(m.w)
                 : "memory");
}

// ---------------------------------------------------------------------------
// K0: detect edge_index element width. For little-endian int64 indices in
// [0, 2^31), every odd 32-bit word is 0. For int32 edge data, odd words are
// uniform node ids in [0, 50000) — 4096 consecutive zeros is impossible.
// ---------------------------------------------------------------------------
__global__ void detect_kernel(const int* __restrict__ ei32)
{
    __shared__ int any_nonzero;
    if (threadIdx.x == 0) any_nonzero = 0;
    __syncthreads();
    for (int i = threadIdx.x; i < 4096; i += blockDim.x)
        if (ei32[2 * i + 1] != 0) any_nonzero = 1;
    __syncthreads();
    if (threadIdx.x == 0) g_is64 = (any_nonzero == 0) ? 1 : 0;
}

// ---------------------------------------------------------------------------
// K1: xw = x @ W ([n,128]@[128,64]) with fused attention-logit epilogue.
// 32 rows/block, 256 threads. Epilogue also zeroes g_den and g_cnt.
// ---------------------------------------------------------------------------
__global__ void gemm_kernel(const float* __restrict__ x,
                            const float* __restrict__ W,
                            const float* __restrict__ att_src,
                            const float* __restrict__ att_dst, int n)
{
    __shared__ float Xs[32][68];   // pad 68: no bank conflicts
    __shared__ float Ws[64][64];

    const int t  = threadIdx.x;
    const int tx = t & 15;         // col group (cols tx*4 .. tx*4+3)
    const int ty = t >> 4;         // row group (rows ty*2, ty*2+1)
    const int row0 = blockIdx.x * 32;

    float acc[2][4] = {{0.f,0.f,0.f,0.f},{0.f,0.f,0.f,0.f}};

    for (int kc = 0; kc < 128; kc += 64) {
        #pragma unroll
        for (int i = 0; i < 4; i++) {
            int idx4 = t + i * 256;
            int kr = idx4 >> 4;
            int c4 = (idx4 & 15) << 2;
            *(float4*)&Ws[kr][c4] = *(const float4*)&W[(kc + kr) * NOUT + c4];
        }
        #pragma unroll
        for (int i = 0; i < 2; i++) {
            int idx4 = t + i * 256;
            int r  = idx4 >> 4;
            int c4 = (idx4 & 15) << 2;
            float4 v = make_float4(0.f, 0.f, 0.f, 0.f);
            if (row0 + r < n)
                v = *(const float4*)&x[(size_t)(row0 + r) * 128 + kc + c4];
            *(float4*)&Xs[r][c4] = v;
        }
        __syncthreads();

        #pragma unroll 16
        for (int k = 0; k < 64; k++) {
            float4 b = *(float4*)&Ws[k][tx << 2];
            float a0 = Xs[ty * 2 + 0][k];
            float a1 = Xs[ty * 2 + 1][k];
            acc[0][0] = fmaf(a0, b.x, acc[0][0]);
            acc[0][1] = fmaf(a0, b.y, acc[0][1]);
            acc[0][2] = fmaf(a0, b.z, acc[0][2]);
            acc[0][3] = fmaf(a0, b.w, acc[0][3]);
            acc[1][0] = fmaf(a1, b.x, acc[1][0]);
            acc[1][1] = fmaf(a1, b.y, acc[1][1]);
            acc[1][2] = fmaf(a1, b.z, acc[1][2]);
            acc[1][3] = fmaf(a1, b.w, acc[1][3]);
        }
        __syncthreads();
    }

    #pragma unroll
    for (int i = 0; i < 2; i++) {
        int r = row0 + ty * 2 + i;
        if (r < n) {
            float4 v = make_float4(acc[i][0], acc[i][1], acc[i][2], acc[i][3]);
            *(float4*)&g_xw[(size_t)r * NOUT + (tx << 2)] = v;
        }
    }

    // Fused attention-logit epilogue; lanes of a (row,head) group differ
    // in lane-id bits 0,1 (same warp), reduce with shfl_xor 1,2.
    const int h  = tx >> 2;
    const int co = (tx & 3) << 2;
    float4 sa = __ldg((const float4*)&att_src[h * NC + co]);
    float4 da = __ldg((const float4*)&att_dst[h * NC + co]);

    #pragma unroll
    for (int i = 0; i < 2; i++) {
        float ps = acc[i][0]*sa.x + acc[i][1]*sa.y + acc[i][2]*sa.z + acc[i][3]*sa.w;
        float pd = acc[i][0]*da.x + acc[i][1]*da.y + acc[i][2]*da.z + acc[i][3]*da.w;
        ps += __shfl_xor_sync(0xffffffffu, ps, 1);
        pd += __shfl_xor_sync(0xffffffffu, pd, 1);
        ps += __shfl_xor_sync(0xffffffffu, ps, 2);
        pd += __shfl_xor_sync(0xffffffffu, pd, 2);
        int r = row0 + ty * 2 + i;
        if ((tx & 3) == 0 && r < n) {
            g_as[r * NH + h]  = ps;
            g_ad[r * NH + h]  = pd;
            g_den[r * NH + h] = 0.f;
            if (h == 0) g_cnt[r] = 0;
        }
    }
}

// ---------------------------------------------------------------------------
// K2: per-edge e = exp(lrelu(a_src[s]+a_dst[d])); store e + (src,dst);
// accumulate denominator; histogram in-degree. Handles int64/int32 edge
// layouts via g_is64. Indices clamped (no-op for valid graphs).
// No max-shift needed: logits ~N(0,2), fp32-safe; alpha shift-invariant.
// ---------------------------------------------------------------------------
__global__ void denom_kernel(const void* __restrict__ eiv, int n, int e)
{
    int i = blockIdx.x * blockDim.x + threadIdx.x;
    int etot = e + n;
    if (i >= etot) return;
    int s, d;
    if (i < e) {
        if (g_is64) {
            const long long* ei = (const long long*)eiv;
            s = (int)__ldg(&ei[i]); d = (int)__ldg(&ei[e + i]);
        } else {
            const int* ei = (const int*)eiv;
            s = __ldg(&ei[i]); d = __ldg(&ei[e + i]);
        }
        s = min(max(s, 0), n - 1);
        d = min(max(d, 0), n - 1);
    } else {
        s = i - e; d = s;
    }
    g_sd[i] = make_int2(s, d);

    float4 as = __ldg(&((const float4*)g_as)[s]);
    float4 ad = __ldg(&((const float4*)g_ad)[d]);
    float4 ev;
    ev.x = __expf(lrelu(as.x + ad.x));
    ev.y = __expf(lrelu(as.y + ad.y));
    ev.z = __expf(lrelu(as.z + ad.z));
    ev.w = __expf(lrelu(as.w + ad.w));
    ((float4*)g_alp)[i] = ev;
    red_add_v4(&g_den[d * NH], ev);
    atomicAdd(&g_cnt[d], 1);
}

// ---------------------------------------------------------------------------
// K3a: per-block exclusive scan of g_cnt (coalesced, full-chip parallel).
// 49 blocks x 1024. Warp shfl scan + smem warp-sum combine.
// ---------------------------------------------------------------------------
__global__ void scan1_kernel(int n)
{
    const int tid  = threadIdx.x;
    const int gid  = blockIdx.x * SCAN_B + tid;
    const int lane = tid & 31;
    const int wid  = tid >> 5;

    int v = (gid < n) ? g_cnt[gid] : 0;
    int x = v;
    #pragma unroll
    for (int o = 1; o < 32; o <<= 1) {
        int y = __shfl_up_sync(0xffffffffu, x, o);
        if (lane >= o) x += y;
    }
    __shared__ int wsum[32];
    if (lane == 31) wsum[wid] = x;
    __syncthreads();
    if (wid == 0) {
        int w = wsum[lane];
        #pragma unroll
        for (int o = 1; o < 32; o <<= 1) {
            int y = __shfl_up_sync(0xffffffffu, w, o);
            if (lane >= o) w += y;
        }
        wsum[lane] = w;
    }
    __syncthreads();
    int incl = x + (wid > 0 ? wsum[wid - 1] : 0);
    if (gid < n) g_start[gid] = incl - v;       // block-local exclusive
    if (tid == SCAN_B - 1) g_bsum[blockIdx.x] = incl;   // block total
}

// ---------------------------------------------------------------------------
// K3b: scan 49 block sums (tiny); also writes g_start[n] = grand total.
// ---------------------------------------------------------------------------
__global__ void scan2_kernel(int nb, int n)
{
    __shared__ int sarr[64];
    int t = threadIdx.x;                        // blockDim = 64
    sarr[t] = (t < nb) ? g_bsum[t] : 0;
    __syncthreads();
    #pragma unroll
    for (int o = 1; o < 64; o <<= 1) {
        int v = (t >= o) ? sarr[t - o] : 0;
        __syncthreads();
        sarr[t] += v;
        __syncthreads();
    }
    if (t < nb) g_boff[t] = (t == 0) ? 0 : sarr[t - 1];
    if (t == 0) g_start[n] = sarr[nb - 1];
}

// ---------------------------------------------------------------------------
// K3c: add block offsets; zero g_cnt for use as the permute cursor.
// ---------------------------------------------------------------------------
__global__ void scan3_kernel(int n)
{
    int gid = blockIdx.x * SCAN_B + threadIdx.x;
    if (gid < n) {
        g_start[gid] += g_boff[blockIdx.x];
        g_cnt[gid] = 0;
    }
}

// ---------------------------------------------------------------------------
// K4: permute edges into dst-CSR order: payload (src, e[4]) per slot.
// Intra-segment order is scheduling-dependent; downstream sums differ only
// in association order (~1e-7), far inside the 1e-3 tolerance.
// ---------------------------------------------------------------------------
__global__ void permute_kernel(int etot)
{
    int i = blockIdx.x * blockDim.x + threadIdx.x;
    if (i >= etot) return;
    int2 sd = __ldg(&g_sd[i]);
    int slot = __ldg(&g_start[sd.y]) + atomicAdd(&g_cnt[sd.y], 1);
    g_csr_src[slot] = sd.x;
    ((float4*)g_csr_e)[slot] = __ldg(&((const float4*)g_alp)[i]);
}

// ---------------------------------------------------------------------------
// K5: aggregate — one warp per destination node. Lane = (edge-group, quad):
// groups 0/1 process alternating edges; lane q owns channels q*4..q*4+3.
// Registers accumulate sum(e * xw[src]); divide by den once; add bias; one
// STG.128 per quad. Zero floating-point atomics.
// ---------------------------------------------------------------------------
__global__ void aggregate_kernel(float* __restrict__ out,
                                 const float* __restrict__ bias, int n)
{
    int w = (blockIdx.x * blockDim.x + threadIdx.x) >> 5;   // dst node
    if (w >= n) return;
    const int lane = threadIdx.x & 31;
    const int grp  = lane >> 4;      // 0 or 1
    const int q    = lane & 15;      // quad
    const int h    = q >> 2;         // head

    const int beg = __ldg(&g_start[w]);
    const int end = __ldg(&g_start[w + 1]);

    float4 acc = make_float4(0.f, 0.f, 0.f, 0.f);
    #pragma unroll 2
    for (int j = beg + grp; j < end; j += 2) {
        int   src = __ldg(&g_csr_src[j]);
        float ev  = __ldg(&g_csr_e[4 * j + h]);
        float4 xw = __ldg((const float4*)&g_xw[(size_t)src * NOUT + (q << 2)]);
        acc.x = fmaf(ev, xw.x, acc.x);
        acc.y = fmaf(ev, xw.y, acc.y);
        acc.z = fmaf(ev, xw.z, acc.z);
        acc.w = fmaf(ev, xw.w, acc.w);
    }
    // combine the two edge-groups
    acc.x += __shfl_xor_sync(0xffffffffu, acc.x, 16);
    acc.y += __shfl_xor_sync(0xffffffffu, acc.y, 16);
    acc.z += __shfl_xor_sync(0xffffffffu, acc.z, 16);
    acc.w += __shfl_xor_sync(0xffffffffu, acc.w, 16);

    if (grp == 0) {
        float den = __ldg(&g_den[w * NH + h]);
        float r = 1.0f / (den + 1e-16f);
        float4 b = __ldg((const float4*)&bias[q << 2]);
        float4 o = make_float4(fmaf(acc.x, r, b.x), fmaf(acc.y, r, b.y),
                               fmaf(acc.z, r, b.z), fmaf(acc.w, r, b.w));
        *(float4*)&out[(size_t)w * NOUT + (q << 2)] = o;
    }
}

// ---------------------------------------------------------------------------
extern "C" void kernel_launch(void* const* d_in, const int* in_sizes, int n_in,
                              void* d_out, int out_size)
{
    const float* x       = (const float*)d_in[0];
    const void*  ei      = d_in[1];                 // [2, E], int64 OR int32 (detected)
    // d_in[2] = edge_attr (ignored by the layer)
    const float* W       = (const float*)d_in[3];
    const float* att_src = (const float*)d_in[4];
    const float* att_dst = (const float*)d_in[5];
    const float* bias    = (const float*)d_in[6];
    float*       out     = (float*)d_out;

    int n = in_sizes[0] / 128;   // 50000
    int e = in_sizes[1] / 2;     // 800000
    int etot = e + n;
    int nb = (n + SCAN_B - 1) / SCAN_B;   // 49

    detect_kernel<<<1, 256>>>((const int*)ei);
    gemm_kernel<<<(n + 31) / 32, 256>>>(x, W, att_src, att_dst, n);
    denom_kernel<<<(etot + 255) / 256, 256>>>(ei, n, e);
    scan1_kernel<<<nb, SCAN_B>>>(n);
    scan2_kernel<<<1, 64>>>(nb, n);
    scan3_kernel<<<nb, SCAN_B>>>(n);
    permute_kernel<<<(etot + 255) / 256, 256>>>(etot);
    aggregate_kernel<<<(n * 32 + 255) / 256, 256>>>(out, bias, n);
}

// round 16
// speedup vs baseline: 1.8568x; 1.1557x over previous
#include <cuda_runtime.h>

// Problem constants (fixed by the dataset): N=50000, NIN=128, NOUT=64, H=4, C=16, E=800000
#define MAXN 50000
#define MAXE 800000
#define MAXET (MAXE + MAXN)   // edges + self-loops
#define NH   4      // heads
#define NC   16     // channels per head
#define NOUT 64     // NH*NC
#define SCAN_B 1024

// Scratch (allocation-free rule: __device__ globals)
__device__ __align__(16) float g_xw[MAXN * NOUT];      // 12.8 MB
__device__ __align__(16) float g_as[MAXN * NH];
__device__ __align__(16) float g_ad[MAXN * NH];
__device__ __align__(16) int   g_cnt[MAXN];            // in-degree / cursor
__device__ __align__(16) int   g_start[MAXN + 1];      // CSR offsets
__device__ __align__(16) int   g_csr_src[MAXET];       // CSR payload: src
__device__ __align__(16) float g_csr_e[MAXET * NH];    // CSR payload: e[4]
__device__ __align__(16) int   g_bsum[64];             // per-block sums
__device__ __align__(16) int   g_boff[64];             // per-block offsets
__device__ int g_is64;                                 // edge_index dtype flag

__device__ __forceinline__ float lrelu(float v) {
    return v > 0.f ? v : 0.2f * v;
}

// ---------------------------------------------------------------------------
// K0: detect edge_index element width. For little-endian int64 indices in
// [0, 2^31), every odd 32-bit word is 0. For int32 edge data, odd words are
// uniform node ids in [0, 50000) — 4096 consecutive zeros is impossible.
// ---------------------------------------------------------------------------
__global__ void detect_kernel(const int* __restrict__ ei32)
{
    __shared__ int any_nonzero;
    if (threadIdx.x == 0) any_nonzero = 0;
    __syncthreads();
    for (int i = threadIdx.x; i < 4096; i += blockDim.x)
        if (ei32[2 * i + 1] != 0) any_nonzero = 1;
    __syncthreads();
    if (threadIdx.x == 0) g_is64 = (any_nonzero == 0) ? 1 : 0;
}

// ---------------------------------------------------------------------------
// K1: xw = x @ W ([n,128]@[128,64]) with fused attention-logit epilogue.
// 32 rows/block, 256 threads. Epilogue also zeroes g_cnt.
// ---------------------------------------------------------------------------
__global__ void gemm_kernel(const float* __restrict__ x,
                            const float* __restrict__ W,
                            const float* __restrict__ att_src,
                            const float* __restrict__ att_dst, int n)
{
    __shared__ float Xs[32][68];   // pad 68: no bank conflicts
    __shared__ float Ws[64][64];

    const int t  = threadIdx.x;
    const int tx = t & 15;         // col group (cols tx*4 .. tx*4+3)
    const int ty = t >> 4;         // row group (rows ty*2, ty*2+1)
    const int row0 = blockIdx.x * 32;

    float acc[2][4] = {{0.f,0.f,0.f,0.f},{0.f,0.f,0.f,0.f}};

    for (int kc = 0; kc < 128; kc += 64) {
        #pragma unroll
        for (int i = 0; i < 4; i++) {
            int idx4 = t + i * 256;
            int kr = idx4 >> 4;
            int c4 = (idx4 & 15) << 2;
            *(float4*)&Ws[kr][c4] = *(const float4*)&W[(kc + kr) * NOUT + c4];
        }
        #pragma unroll
        for (int i = 0; i < 2; i++) {
            int idx4 = t + i * 256;
            int r  = idx4 >> 4;
            int c4 = (idx4 & 15) << 2;
            float4 v = make_float4(0.f, 0.f, 0.f, 0.f);
            if (row0 + r < n)
                v = *(const float4*)&x[(size_t)(row0 + r) * 128 + kc + c4];
            *(float4*)&Xs[r][c4] = v;
        }
        __syncthreads();

        #pragma unroll 16
        for (int k = 0; k < 64; k++) {
            float4 b = *(float4*)&Ws[k][tx << 2];
            float a0 = Xs[ty * 2 + 0][k];
            float a1 = Xs[ty * 2 + 1][k];
            acc[0][0] = fmaf(a0, b.x, acc[0][0]);
            acc[0][1] = fmaf(a0, b.y, acc[0][1]);
            acc[0][2] = fmaf(a0, b.z, acc[0][2]);
            acc[0][3] = fmaf(a0, b.w, acc[0][3]);
            acc[1][0] = fmaf(a1, b.x, acc[1][0]);
            acc[1][1] = fmaf(a1, b.y, acc[1][1]);
            acc[1][2] = fmaf(a1, b.z, acc[1][2]);
            acc[1][3] = fmaf(a1, b.w, acc[1][3]);
        }
        __syncthreads();
    }

    #pragma unroll
    for (int i = 0; i < 2; i++) {
        int r = row0 + ty * 2 + i;
        if (r < n) {
            float4 v = make_float4(acc[i][0], acc[i][1], acc[i][2], acc[i][3]);
            *(float4*)&g_xw[(size_t)r * NOUT + (tx << 2)] = v;
        }
    }

    // Fused attention-logit epilogue; lanes of a (row,head) group differ
    // in lane-id bits 0,1 (same warp), reduce with shfl_xor 1,2.
    const int h  = tx >> 2;
    const int co = (tx & 3) << 2;
    float4 sa = __ldg((const float4*)&att_src[h * NC + co]);
    float4 da = __ldg((const float4*)&att_dst[h * NC + co]);

    #pragma unroll
    for (int i = 0; i < 2; i++) {
        float ps = acc[i][0]*sa.x + acc[i][1]*sa.y + acc[i][2]*sa.z + acc[i][3]*sa.w;
        float pd = acc[i][0]*da.x + acc[i][1]*da.y + acc[i][2]*da.z + acc[i][3]*da.w;
        ps += __shfl_xor_sync(0xffffffffu, ps, 1);
        pd += __shfl_xor_sync(0xffffffffu, pd, 1);
        ps += __shfl_xor_sync(0xffffffffu, ps, 2);
        pd += __shfl_xor_sync(0xffffffffu, pd, 2);
        int r = row0 + ty * 2 + i;
        if ((tx & 3) == 0 && r < n) {
            g_as[r * NH + h]  = ps;
            g_ad[r * NH + h]  = pd;
            if (h == 0) g_cnt[r] = 0;
        }
    }
}

// ---------------------------------------------------------------------------
// K2: in-degree histogram. Reads ONLY the dst half of edge_index.
// ---------------------------------------------------------------------------
__global__ void count_kernel(const void* __restrict__ eiv, int n, int e)
{
    int i = blockIdx.x * blockDim.x + threadIdx.x;
    int etot = e + n;
    if (i >= etot) return;
    int d;
    if (i < e) {
        if (g_is64) d = (int)__ldg(&((const long long*)eiv)[e + i]);
        else        d = __ldg(&((const int*)eiv)[e + i]);
        d = min(max(d, 0), n - 1);
    } else {
        d = i - e;
    }
    atomicAdd(&g_cnt[d], 1);
}

// ---------------------------------------------------------------------------
// K3a: per-block exclusive scan of g_cnt (coalesced, full-chip parallel).
// ---------------------------------------------------------------------------
__global__ void scan1_kernel(int n)
{
    const int tid  = threadIdx.x;
    const int gid  = blockIdx.x * SCAN_B + tid;
    const int lane = tid & 31;
    const int wid  = tid >> 5;

    int v = (gid < n) ? g_cnt[gid] : 0;
    int x = v;
    #pragma unroll
    for (int o = 1; o < 32; o <<= 1) {
        int y = __shfl_up_sync(0xffffffffu, x, o);
        if (lane >= o) x += y;
    }
    __shared__ int wsum[32];
    if (lane == 31) wsum[wid] = x;
    __syncthreads();
    if (wid == 0) {
        int w = wsum[lane];
        #pragma unroll
        for (int o = 1; o < 32; o <<= 1) {
            int y = __shfl_up_sync(0xffffffffu, w, o);
            if (lane >= o) w += y;
        }
        wsum[lane] = w;
    }
    __syncthreads();
    int incl = x + (wid > 0 ? wsum[wid - 1] : 0);
    if (gid < n) g_start[gid] = incl - v;       // block-local exclusive
    if (tid == SCAN_B - 1) g_bsum[blockIdx.x] = incl;   // block total
}

// ---------------------------------------------------------------------------
// K3b: scan the 49 block sums; also writes g_start[n] = grand total.
// ---------------------------------------------------------------------------
__global__ void scan2_kernel(int nb, int n)
{
    __shared__ int sarr[64];
    int t = threadIdx.x;                        // blockDim = 64
    sarr[t] = (t < nb) ? g_bsum[t] : 0;
    __syncthreads();
    #pragma unroll
    for (int o = 1; o < 64; o <<= 1) {
        int v = (t >= o) ? sarr[t - o] : 0;
        __syncthreads();
        sarr[t] += v;
        __syncthreads();
    }
    if (t < nb) g_boff[t] = (t == 0) ? 0 : sarr[t - 1];
    if (t == 0) g_start[n] = sarr[nb - 1];
}

// ---------------------------------------------------------------------------
// K3c: add block offsets; zero g_cnt for use as the build cursor.
// ---------------------------------------------------------------------------
__global__ void scan3_kernel(int n)
{
    int gid = blockIdx.x * SCAN_B + threadIdx.x;
    if (gid < n) {
        g_start[gid] += g_boff[blockIdx.x];
        g_cnt[gid] = 0;
    }
}

// ---------------------------------------------------------------------------
// K4: build CSR directly: per edge compute e = exp(lrelu(a_src[s]+a_dst[d]))
// and write (src, e[4]) straight into its CSR slot. No intermediate g_sd /
// g_alp arrays, no separate permute pass, no f32 atomics (denominator is
// recovered for free inside aggregate). Intra-segment order is scheduling-
// dependent -> downstream sums differ only in association order (~1e-7).
// No max-shift needed: logits ~N(0,2), fp32-safe; alpha shift-invariant.
// ---------------------------------------------------------------------------
__global__ void build_kernel(const void* __restrict__ eiv, int n, int e)
{
    int i = blockIdx.x * blockDim.x + threadIdx.x;
    int etot = e + n;
    if (i >= etot) return;
    int s, d;
    if (i < e) {
        if (g_is64) {
            const long long* ei = (const long long*)eiv;
            s = (int)__ldg(&ei[i]); d = (int)__ldg(&ei[e + i]);
        } else {
            const int* ei = (const int*)eiv;
            s = __ldg(&ei[i]); d = __ldg(&ei[e + i]);
        }
        s = min(max(s, 0), n - 1);
        d = min(max(d, 0), n - 1);
    } else {
        s = i - e; d = s;
    }

    int slot = __ldg(&g_start[d]) + atomicAdd(&g_cnt[d], 1);

    float4 as = __ldg(&((const float4*)g_as)[s]);
    float4 ad = __ldg(&((const float4*)g_ad)[d]);
    float4 ev;
    ev.x = __expf(lrelu(as.x + ad.x));
    ev.y = __expf(lrelu(as.y + ad.y));
    ev.z = __expf(lrelu(as.z + ad.z));
    ev.w = __expf(lrelu(as.w + ad.w));

    g_csr_src[slot] = s;
    ((float4*)g_csr_e)[slot] = ev;
}

// ---------------------------------------------------------------------------
// K5: aggregate — one warp per destination node. Lane = (edge-group, quad):
// groups 0/1 process alternating edges; lane q owns channels q*4..q*4+3.
// Registers accumulate num = sum(e*xw[src]) AND den = sum(e) (softmax
// denominator for free — no global atomics anywhere). Final:
// out = num/(den+1e-16) + bias, one STG.128 per quad.
// ---------------------------------------------------------------------------
__global__ void aggregate_kernel(float* __restrict__ out,
                                 const float* __restrict__ bias, int n)
{
    int w = (blockIdx.x * blockDim.x + threadIdx.x) >> 5;   // dst node
    if (w >= n) return;
    const int lane = threadIdx.x & 31;
    const int grp  = lane >> 4;      // 0 or 1
    const int q    = lane & 15;      // quad
    const int h    = q >> 2;         // head

    const int beg = __ldg(&g_start[w]);
    const int end = __ldg(&g_start[w + 1]);

    float4 num = make_float4(0.f, 0.f, 0.f, 0.f);
    float  den = 0.f;
    #pragma unroll 2
    for (int j = beg + grp; j < end; j += 2) {
        int   src = __ldg(&g_csr_src[j]);
        float ev  = __ldg(&g_csr_e[4 * j + h]);
        float4 xw = __ldg((const float4*)&g_xw[(size_t)src * NOUT + (q << 2)]);
        num.x = fmaf(ev, xw.x, num.x);
        num.y = fmaf(ev, xw.y, num.y);
        num.z = fmaf(ev, xw.z, num.z);
        num.w = fmaf(ev, xw.w, num.w);
        den  += ev;
    }
    // combine the two edge-groups
    num.x += __shfl_xor_sync(0xffffffffu, num.x, 16);
    num.y += __shfl_xor_sync(0xffffffffu, num.y, 16);
    num.z += __shfl_xor_sync(0xffffffffu, num.z, 16);
    num.w += __shfl_xor_sync(0xffffffffu, num.w, 16);
    den   += __shfl_xor_sync(0xffffffffu, den,   16);

    if (grp == 0) {
        float r = 1.0f / (den + 1e-16f);
        float4 b = __ldg((const float4*)&bias[q << 2]);
        float4 o = make_float4(fmaf(num.x, r, b.x), fmaf(num.y, r, b.y),
                               fmaf(num.z, r, b.z), fmaf(num.w, r, b.w));
        *(float4*)&out[(size_t)w * NOUT + (q << 2)] = o;
    }
}

// ---------------------------------------------------------------------------
extern "C" void kernel_launch(void* const* d_in, const int* in_sizes, int n_in,
                              void* d_out, int out_size)
{
    const float* x       = (const float*)d_in[0];
    const void*  ei      = d_in[1];                 // [2, E], int64 OR int32 (detected)
    // d_in[2] = edge_attr (ignored by the layer)
    const float* W       = (const float*)d_in[3];
    const float* att_src = (const float*)d_in[4];
    const float* att_dst = (const float*)d_in[5];
    const float* bias    = (const float*)d_in[6];
    float*       out     = (float*)d_out;

    int n = in_sizes[0] / 128;   // 50000
    int e = in_sizes[1] / 2;     // 800000
    int etot = e + n;
    int nb = (n + SCAN_B - 1) / SCAN_B;   // 49

    detect_kernel<<<1, 256>>>((const int*)ei);
    gemm_kernel<<<(n + 31) / 32, 256>>>(x, W, att_src, att_dst, n);
    count_kernel<<<(etot + 255) / 256, 256>>>(ei, n, e);
    scan1_kernel<<<nb, SCAN_B>>>(n);
    scan2_kernel<<<1, 64>>>(nb, n);
    scan3_kernel<<<nb, SCAN_B>>>(n);
    build_kernel<<<(etot + 255) / 256, 256>>>(ei, n, e);
    aggregate_kernel<<<(n * 32 + 255) / 256, 256>>>(out, bias, n);
}